// round 15
// baseline (speedup 1.0000x reference)
#include <cuda_runtime.h>
#include <math.h>
#include <stdint.h>

// Problem constants
#define Bb   4
#define Tt   2048
#define Cc   1024
#define Hh   16
#define HSd  64
#define Mm   (Bb * Tt)      // 8192
#define NQKV (3 * Cc)       // 3072

// Scratch (static device globals: allocation rules forbid cudaMalloc)
__device__ float g_qkv[(size_t)Mm * NQKV];     // [B*T, 3C] tf32 (q pre-scaled by SC_Q)
__device__ float g_attn[(size_t)Mm * Cc];      // [B*T, C] tf32 attention out
__device__ float g_xc[(size_t)Mm * Cc];        // x, tf32
__device__ float g_wqkv_c[(size_t)Cc * NQKV];  // W_qkv, tf32, [K][N]
__device__ float g_wproj_c[(size_t)Cc * Cc];   // W_proj, tf32, [K][N]

// ---------------------------------------------------------------------------
// helpers
// ---------------------------------------------------------------------------
static __device__ __forceinline__ uint32_t f2tf32(float x) {
    uint32_t y;
    asm("cvt.rna.tf32.f32 %0, %1;" : "=r"(y) : "f"(x));
    return y;
}

static __device__ __forceinline__ float exp2fast(float x) {
    float y;
    asm("ex2.approx.f32 %0, %1;" : "=f"(y) : "f"(x));
    return y;
}

static __device__ __forceinline__ void mma_tf32(float c[4], const uint32_t a[4],
                                                const uint32_t b[2]) {
    asm volatile(
        "mma.sync.aligned.m16n8k8.row.col.f32.tf32.tf32.f32 "
        "{%0,%1,%2,%3}, {%4,%5,%6,%7}, {%8,%9}, {%0,%1,%2,%3};\n"
        : "+f"(c[0]), "+f"(c[1]), "+f"(c[2]), "+f"(c[3])
        : "r"(a[0]), "r"(a[1]), "r"(a[2]), "r"(a[3]), "r"(b[0]), "r"(b[1]));
}

static __device__ __forceinline__ void cp_async16(uint32_t smem_dst,
                                                  const void* gsrc) {
    asm volatile("cp.async.cg.shared.global [%0], [%1], 16;"
                 :: "r"(smem_dst), "l"(gsrc) : "memory");
}
static __device__ __forceinline__ void cp_async_commit() {
    asm volatile("cp.async.commit_group;" ::: "memory");
}
static __device__ __forceinline__ void cp_async_wait0() {
    asm volatile("cp.async.wait_group 0;" ::: "memory");
}
static __device__ __forceinline__ void cp_async_wait1() {
    asm volatile("cp.async.wait_group 1;" ::: "memory");
}

#define SC_Q (0.125f * 1.4426950408889634f)   // (1/sqrt(64)) * log2(e)

// ---------------------------------------------------------------------------
// Prepass: elementwise tf32-round (vectorized)
// ---------------------------------------------------------------------------
__global__ void cvt_kernel(const float* __restrict__ in, float* __restrict__ out,
                           int n4)
{
    int i = blockIdx.x * blockDim.x + threadIdx.x;
    if (i < n4) {
        float4 v = ((const float4*)in)[i];
        v.x = __uint_as_float(f2tf32(v.x));
        v.y = __uint_as_float(f2tf32(v.y));
        v.z = __uint_as_float(f2tf32(v.z));
        v.w = __uint_as_float(f2tf32(v.w));
        ((float4*)out)[i] = v;
    }
}

// ---------------------------------------------------------------------------
// tf32 tensor-core GEMM: C = A @ B (+ epilogue). Inputs ALREADY tf32-rounded.
// CTA = 128 threads (4 warps, 2x2), CTA tile 128x128, warp tile 64x64, BK=32.
// BOTH operands staged via cp.async; 2-stage pipeline; 3 CTAs/SM.
// A smem: [row][32], 16B-chunk swizzle c' = c ^ (row&7). B: [k][128],
// chunk swizzle ch' = ch ^ (2*(k&3)). Conflict-free fragment reads.
// MODE 0 (QKV): cols < Cc (q) scaled by SC_Q; outputs tf32-rounded.
// MODE 1 (proj): + bias, fp32 out.
// Dyn smem: 64 KB.
// ---------------------------------------------------------------------------
#define GEMM_SMEM (16384 * 4)

template <int MODE>
__global__ __launch_bounds__(128, 3)
void tgemm_kernel(const float* __restrict__ A, const float* __restrict__ B,
                  const float* __restrict__ bias, float* __restrict__ C,
                  int M, int N, int K)
{
    extern __shared__ float smg[];
    const uint32_t sbase = (uint32_t)__cvta_generic_to_shared(smg);

    const int tid  = threadIdx.x;
    const int lane = tid & 31;
    const int warp = tid >> 5;
    const int m0 = blockIdx.y * 128;
    const int n0 = blockIdx.x * 128;
    const int wr = (warp & 1) * 64;   // warp m offset
    const int wn = (warp >> 1) * 64;  // warp n offset
    const int r0 = lane >> 2;         // 0..7
    const int c0 = lane & 3;          // 0..3
    const int xr = 8 * c0;            // read-side B swizzle

    float c[4][8][4];
    #pragma unroll
    for (int mi = 0; mi < 4; mi++)
        #pragma unroll
        for (int ni = 0; ni < 8; ni++)
            #pragma unroll
            for (int j = 0; j < 4; j++) c[mi][ni][j] = 0.0f;

    const float* Abase = A + (size_t)m0 * K;
    const float* Bbase = B + n0;
    const int nk = K / 32;

    auto cpStage = [&](int kb, int s) {
        #pragma unroll
        for (int i = 0; i < 8; i++) {
            int id  = i * 128 + tid;
            int row = id >> 3;
            int ch  = id & 7;
            uint32_t dst = sbase +
                (uint32_t)(s * 4096 + row * 32 + ((ch ^ (row & 7)) << 2)) * 4;
            cp_async16(dst, Abase + (size_t)row * K + kb * 32 + ch * 4);
        }
        #pragma unroll
        for (int i = 0; i < 8; i++) {
            int id  = i * 128 + tid;
            int row = id >> 5;
            int ch  = id & 31;
            uint32_t dst = sbase +
                (uint32_t)(8192 + s * 4096 + row * 128 + ((ch ^ (2 * (row & 3))) << 2)) * 4;
            cp_async16(dst, Bbase + (size_t)(kb * 32 + row) * N + ch * 4);
        }
        cp_async_commit();
    };

    // Prologue: stage blocks 0 and 1
    cpStage(0, 0);
    cpStage(1, 1);

    for (int kb = 0; kb < nk; kb++) {
        const int buf = kb & 1;
        if (kb + 1 < nk) cp_async_wait1(); else cp_async_wait0();
        __syncthreads();

        const float* As = smg + buf * 4096;
        const float* Bs = smg + 8192 + buf * 4096;
        #pragma unroll
        for (int g = 0; g < 4; g++) {
            uint32_t b[8][2];
            #pragma unroll
            for (int ni = 0; ni < 8; ni++) {
                int coln = (wn + ni * 8 + r0) ^ xr;
                b[ni][0] = __float_as_uint(Bs[(g * 8 + c0)     * 128 + coln]);
                b[ni][1] = __float_as_uint(Bs[(g * 8 + c0 + 4) * 128 + coln]);
            }
            const int sw0 = (((2 * g)     ^ r0) << 2) + c0;
            const int sw1 = (((2 * g + 1) ^ r0) << 2) + c0;
            #pragma unroll
            for (int mi = 0; mi < 4; mi++) {
                const int ra = (wr + mi * 16 + r0) * 32;
                uint32_t a[4];
                a[0] = __float_as_uint(As[ra       + sw0]);
                a[1] = __float_as_uint(As[ra + 256 + sw0]);   // +8 rows
                a[2] = __float_as_uint(As[ra       + sw1]);
                a[3] = __float_as_uint(As[ra + 256 + sw1]);
                #pragma unroll
                for (int ni = 0; ni < 8; ni++) mma_tf32(c[mi][ni], a, b[ni]);
            }
        }

        __syncthreads();
        if (kb + 2 < nk) cpStage(kb + 2, buf);
    }

    // Epilogue
    #pragma unroll
    for (int mi = 0; mi < 4; mi++) {
        #pragma unroll
        for (int ni = 0; ni < 8; ni++) {
            int row = m0 + wr + mi * 16 + r0;
            int col = n0 + wn + ni * 8 + 2 * c0;
            float2 v0, v1;
            v0.x = c[mi][ni][0]; v0.y = c[mi][ni][1];
            v1.x = c[mi][ni][2]; v1.y = c[mi][ni][3];
            if (MODE == 0) {
                const float sc = (col < Cc) ? SC_Q : 1.0f;
                v0.x = __uint_as_float(f2tf32(v0.x * sc));
                v0.y = __uint_as_float(f2tf32(v0.y * sc));
                v1.x = __uint_as_float(f2tf32(v1.x * sc));
                v1.y = __uint_as_float(f2tf32(v1.y * sc));
            } else {
                float bx = bias[col], by = bias[col + 1];
                v0.x += bx; v0.y += by;
                v1.x += bx; v1.y += by;
            }
            *(float2*)(C + (size_t)row * N + col)       = v0;
            *(float2*)(C + (size_t)(row + 8) * N + col) = v1;
        }
    }
}

// ---------------------------------------------------------------------------
// Tensor-core flash attention (tf32 mma, causal).
// 512 threads / 16 warps, warp tile = 16 q-rows (halved per-thread state ->
// <=128 regs -> 16 warps resident per SM, 2x the old occupancy).
// cp.async double-buffered 64-key K/V tiles; per-warp causal skip.
// qkv is tf32 with q pre-scaled; output tf32-rounded.
// Smem: 2 x (K[64*68] + V[64*68]) + 16 warps x P[16*36] = 104 KB.
// ---------------------------------------------------------------------------
#define KVF   (64 * 68)                 // floats per K (or V) tile
#define ATT_SMEM ((4 * KVF + 16 * 16 * 36) * 4)

__global__ __launch_bounds__(512, 1)
void flash_tc_kernel(const float* __restrict__ qkv, float* __restrict__ out)
{
    extern __shared__ float sm[];
    const uint32_t sbase = (uint32_t)__cvta_generic_to_shared(sm);

    const int tid  = threadIdx.x;
    const int lane = tid & 31;
    const int warp = tid >> 5;        // 0..15
    const int r0 = lane >> 2;         // 0..7
    const int c0 = lane & 3;          // 0..3

    float* Phi = sm + 4 * KVF + warp * (16 * 36);

    const int bh = blockIdx.x;        // 0..63
    const int b  = bh >> 4;
    const int h  = bh & 15;
    const int q0 = (7 - (int)blockIdx.y) * 256;   // heavy blocks first
    const int wr = warp * 16;         // warp's 16 q-rows within the 256 block

    // Q fragments -> registers (already tf32 + scaled); 16 rows
    uint32_t qa[8][4];
    {
        const float* qb = qkv + ((size_t)(b * Tt + q0 + wr)) * NQKV + h * HSd;
        #pragma unroll
        for (int ks = 0; ks < 8; ks++) {
            const float* p0 = qb + (size_t)r0       * NQKV + ks * 8 + c0;
            const float* p1 = qb + (size_t)(8 + r0) * NQKV + ks * 8 + c0;
            qa[ks][0] = __float_as_uint(p0[0]);
            qa[ks][1] = __float_as_uint(p1[0]);
            qa[ks][2] = __float_as_uint(p0[4]);
            qa[ks][3] = __float_as_uint(p1[4]);
        }
    }

    float o[8][4];
    #pragma unroll
    for (int ni = 0; ni < 8; ni++)
        #pragma unroll
        for (int j = 0; j < 4; j++) o[ni][j] = 0.0f;
    float mrow[2] = {-1e30f, -1e30f};
    float lrow[2] = {0.0f, 0.0f};

    const float* kgb = qkv + ((size_t)b * Tt) * NQKV + Cc + h * HSd;
    const float* vgb = kgb + Cc;

    const int ntiles = q0 / 64 + 4;
    const int firstMaskTile = (q0 + wr) >> 6;    // per-warp
    const int lastRow = q0 + wr + 15;            // last q-row this warp owns

    // cp.async K/V staging: 2048 16B-chunks total, 512 threads x 4
    auto cpKV = [&](int kt, int s) {
        const float* kg = kgb + (size_t)(kt * 64) * NQKV;
        const float* vg = vgb + (size_t)(kt * 64) * NQKV;
        #pragma unroll
        for (int i = 0; i < 2; i++) {
            int idx = i * 512 + tid;          // 0..1023
            int row = idx >> 4;
            int cc4 = (idx & 15) << 2;
            uint32_t doff = (uint32_t)(s * 2 * KVF + row * 68 + cc4) * 4;
            cp_async16(sbase + doff,           kg + (size_t)row * NQKV + cc4);
            cp_async16(sbase + doff + KVF * 4, vg + (size_t)row * NQKV + cc4);
        }
        cp_async_commit();
    };

    cpKV(0, 0);

    for (int kt = 0; kt < ntiles; kt++) {
        const int buf = kt & 1;
        if (kt + 1 < ntiles) { cpKV(kt + 1, buf ^ 1); cp_async_wait1(); }
        else cp_async_wait0();
        __syncthreads();

        // Per-warp causal skip: tile fully above this warp's diagonal
        if (kt * 64 <= lastRow) {
            const float* Ksm = sm + buf * 2 * KVF;
            const float* Vsm = Ksm + KVF;

            // S = Q K^T   (16 q-rows x 64 keys)
            float s[8][4];
            #pragma unroll
            for (int ni = 0; ni < 8; ni++)
                #pragma unroll
                for (int j = 0; j < 4; j++) s[ni][j] = 0.0f;

            #pragma unroll
            for (int ks = 0; ks < 8; ks++) {
                #pragma unroll
                for (int ni = 0; ni < 8; ni++) {
                    uint32_t bb[2];
                    bb[0] = __float_as_uint(Ksm[(ni * 8 + r0) * 68 + ks * 8 + c0]);
                    bb[1] = __float_as_uint(Ksm[(ni * 8 + r0) * 68 + ks * 8 + c0 + 4]);
                    mma_tf32(s[ni], qa[ks], bb);
                }
            }

            // Causal mask (per-warp diagonal tiles only)
            if (kt >= firstMaskTile) {
                int row = q0 + wr + r0;
                #pragma unroll
                for (int ni = 0; ni < 8; ni++) {
                    int key = kt * 64 + ni * 8 + 2 * c0;
                    if (key     > row)     s[ni][0] = -1e30f;
                    if (key + 1 > row)     s[ni][1] = -1e30f;
                    if (key     > row + 8) s[ni][2] = -1e30f;
                    if (key + 1 > row + 8) s[ni][3] = -1e30f;
                }
            }

            // Online softmax (exp2 domain); s becomes p
            #pragma unroll
            for (int h2 = 0; h2 < 2; h2++) {
                float mx = -1e30f;
                #pragma unroll
                for (int ni = 0; ni < 8; ni++)
                    mx = fmaxf(mx, fmaxf(s[ni][2 * h2], s[ni][2 * h2 + 1]));
                mx = fmaxf(mx, __shfl_xor_sync(0xffffffffu, mx, 1));
                mx = fmaxf(mx, __shfl_xor_sync(0xffffffffu, mx, 2));
                float mnew = fmaxf(mrow[h2], mx);
                float corr = exp2fast(mrow[h2] - mnew);
                mrow[h2] = mnew;
                float psum = 0.0f;
                #pragma unroll
                for (int ni = 0; ni < 8; ni++) {
                    float p0 = exp2fast(s[ni][2 * h2]     - mnew);
                    float p1 = exp2fast(s[ni][2 * h2 + 1] - mnew);
                    s[ni][2 * h2]     = p0;
                    s[ni][2 * h2 + 1] = p1;
                    psum += p0 + p1;
                }
                lrow[h2] = lrow[h2] * corr + psum;
                #pragma unroll
                for (int ni = 0; ni < 8; ni++) {
                    o[ni][2 * h2]     *= corr;
                    o[ni][2 * h2 + 1] *= corr;
                }
            }

            // O += P V, two 32-key halves (P tf32 via per-warp smem)
            #pragma unroll
            for (int hk = 0; hk < 2; hk++) {
                #pragma unroll
                for (int h2 = 0; h2 < 2; h2++) {
                    int rloc = h2 * 8 + r0;
                    #pragma unroll
                    for (int j = 0; j < 4; j++) {
                        float h0 = __uint_as_float(f2tf32(s[hk * 4 + j][2 * h2]));
                        float h1 = __uint_as_float(f2tf32(s[hk * 4 + j][2 * h2 + 1]));
                        *(float2*)&Phi[rloc * 36 + j * 8 + 2 * c0] = make_float2(h0, h1);
                    }
                }
                __syncwarp();
                #pragma unroll
                for (int ks = 0; ks < 4; ks++) {
                    uint32_t ah[4];
                    ah[0] = __float_as_uint(Phi[r0 * 36       + ks * 8 + c0]);
                    ah[1] = __float_as_uint(Phi[(r0 + 8) * 36 + ks * 8 + c0]);
                    ah[2] = __float_as_uint(Phi[r0 * 36       + ks * 8 + c0 + 4]);
                    ah[3] = __float_as_uint(Phi[(r0 + 8) * 36 + ks * 8 + c0 + 4]);
                    #pragma unroll
                    for (int ni = 0; ni < 8; ni++) {
                        uint32_t bb[2];
                        int vrow = hk * 32 + ks * 8 + c0;
                        bb[0] = __float_as_uint(Vsm[vrow * 68 + ni * 8 + r0]);
                        bb[1] = __float_as_uint(Vsm[(vrow + 4) * 68 + ni * 8 + r0]);
                        mma_tf32(o[ni], ah, bb);
                    }
                }
                __syncwarp();
            }
        }

        __syncthreads();   // all warps done with buf before next prefetch overwrites it
    }

    // Final normalize + tf32-round + write
    float linv[2];
    #pragma unroll
    for (int h2 = 0; h2 < 2; h2++) {
        float l = lrow[h2];
        l += __shfl_xor_sync(0xffffffffu, l, 1);
        l += __shfl_xor_sync(0xffffffffu, l, 2);
        linv[h2] = 1.0f / l;
    }
    float* ob = out + ((size_t)(b * Tt + q0 + wr)) * Cc + h * HSd;
    #pragma unroll
    for (int h2 = 0; h2 < 2; h2++) {
        int rloc = h2 * 8 + r0;
        float inv = linv[h2];
        #pragma unroll
        for (int ni = 0; ni < 8; ni++) {
            float2 v;
            v.x = __uint_as_float(f2tf32(o[ni][2 * h2]     * inv));
            v.y = __uint_as_float(f2tf32(o[ni][2 * h2 + 1] * inv));
            *(float2*)(ob + (size_t)rloc * Cc + ni * 8 + 2 * c0) = v;
        }
    }
}

// ---------------------------------------------------------------------------
extern "C" void kernel_launch(void* const* d_in, const int* in_sizes, int n_in,
                              void* d_out, int out_size)
{
    const float* x     = (const float*)d_in[0];   // [B,T,C]
    const float* Wqkv  = (const float*)d_in[1];   // [C,3C]
    const float* Wproj = (const float*)d_in[2];   // [C,C]
    const float* bproj = (const float*)d_in[3];   // [C]
    float* out = (float*)d_out;                   // [B,T,C]

    float *qkv, *attn, *xc, *wqkvc, *wprojc;
    cudaGetSymbolAddress((void**)&qkv,    g_qkv);
    cudaGetSymbolAddress((void**)&attn,   g_attn);
    cudaGetSymbolAddress((void**)&xc,     g_xc);
    cudaGetSymbolAddress((void**)&wqkvc,  g_wqkv_c);
    cudaGetSymbolAddress((void**)&wprojc, g_wproj_c);

    cudaFuncSetAttribute(tgemm_kernel<0>,
                         cudaFuncAttributeMaxDynamicSharedMemorySize, GEMM_SMEM);
    cudaFuncSetAttribute(tgemm_kernel<1>,
                         cudaFuncAttributeMaxDynamicSharedMemorySize, GEMM_SMEM);
    cudaFuncSetAttribute(flash_tc_kernel,
                         cudaFuncAttributeMaxDynamicSharedMemorySize, ATT_SMEM);

    // Prepass: tf32-round x + both weights (elementwise, out-of-loop)
    cvt_kernel<<<(Mm * Cc / 4 + 255) / 256, 256>>>(x, xc, Mm * Cc / 4);
    cvt_kernel<<<(Cc * NQKV / 4 + 255) / 256, 256>>>(Wqkv, wqkvc, Cc * NQKV / 4);
    cvt_kernel<<<(Cc * Cc / 4 + 255) / 256, 256>>>(Wproj, wprojc, Cc * Cc / 4);

    // 1) QKV projection: [8192,1024] @ [1024,3072] -> tf32 qkv (q pre-scaled)
    tgemm_kernel<0><<<dim3(NQKV / 128, Mm / 128), 128, GEMM_SMEM>>>(
        xc, wqkvc, nullptr, qkv, Mm, NQKV, Cc);
    // 2) Causal flash attention -> tf32 [B,T,C]
    flash_tc_kernel<<<dim3(Bb * Hh, Tt / 256), 512, ATT_SMEM>>>(qkv, attn);
    // 3) Output projection + bias: [8192,1024] @ [1024,1024]
    tgemm_kernel<1><<<dim3(Cc / 128, Mm / 128), 128, GEMM_SMEM>>>(
        attn, wprojc, bproj, out, Mm, Cc, Cc);
}

// round 16
// speedup vs baseline: 1.0702x; 1.0702x over previous
#include <cuda_runtime.h>
#include <math.h>
#include <stdint.h>

// Problem constants
#define Bb   4
#define Tt   2048
#define Cc   1024
#define Hh   16
#define HSd  64
#define Mm   (Bb * Tt)      // 8192
#define NQKV (3 * Cc)       // 3072

// Scratch (static device globals: allocation rules forbid cudaMalloc)
__device__ float g_qkv[(size_t)Mm * NQKV];     // [B*T, 3C] tf32 (q pre-scaled by SC_Q)
__device__ float g_attn[(size_t)Mm * Cc];      // [B*T, C] tf32 attention out, K-PERMUTED
__device__ float g_xc[(size_t)Mm * Cc];        // x, tf32, K-PERMUTED
__device__ float g_wqkv_c[(size_t)NQKV * Cc];  // W_qkv^T, tf32, [N][K] K-PERMUTED
__device__ float g_wproj_c[(size_t)Cc * Cc];   // W_proj^T, tf32, [N][K] K-PERMUTED

// Octet permutation: within each group of 8 k's, store order k0,k4,k1,k5,k2,k6,k3,k7.
// perm(w) = 2*(w&3) + ((w>>2)&1). Pair (k, k+4) lands at words (2k&7.., adjacent).

// ---------------------------------------------------------------------------
// helpers
// ---------------------------------------------------------------------------
static __device__ __forceinline__ uint32_t f2tf32(float x) {
    uint32_t y;
    asm("cvt.rna.tf32.f32 %0, %1;" : "=r"(y) : "f"(x));
    return y;
}

static __device__ __forceinline__ float exp2fast(float x) {
    float y;
    asm("ex2.approx.f32 %0, %1;" : "=f"(y) : "f"(x));
    return y;
}

static __device__ __forceinline__ void mma_tf32(float c[4], const uint32_t a[4],
                                                const uint32_t b[2]) {
    asm volatile(
        "mma.sync.aligned.m16n8k8.row.col.f32.tf32.tf32.f32 "
        "{%0,%1,%2,%3}, {%4,%5,%6,%7}, {%8,%9}, {%0,%1,%2,%3};\n"
        : "+f"(c[0]), "+f"(c[1]), "+f"(c[2]), "+f"(c[3])
        : "r"(a[0]), "r"(a[1]), "r"(a[2]), "r"(a[3]), "r"(b[0]), "r"(b[1]));
}

static __device__ __forceinline__ void cp_async16(uint32_t smem_dst,
                                                  const void* gsrc) {
    asm volatile("cp.async.cg.shared.global [%0], [%1], 16;"
                 :: "r"(smem_dst), "l"(gsrc) : "memory");
}
static __device__ __forceinline__ void cp_async_commit() {
    asm volatile("cp.async.commit_group;" ::: "memory");
}
static __device__ __forceinline__ void cp_async_wait0() {
    asm volatile("cp.async.wait_group 0;" ::: "memory");
}
static __device__ __forceinline__ void cp_async_wait1() {
    asm volatile("cp.async.wait_group 1;" ::: "memory");
}

#define SC_Q (0.125f * 1.4426950408889634f)   // (1/sqrt(64)) * log2(e)

// ---------------------------------------------------------------------------
// Prepass: tf32-round + octet-permute along K (elementwise over octets)
// ---------------------------------------------------------------------------
__global__ void cvt_perm_kernel(const float* __restrict__ in,
                                float* __restrict__ out, int n8)
{
    int i = blockIdx.x * blockDim.x + threadIdx.x;   // octet index
    if (i < n8) {
        float4 v0 = ((const float4*)in)[2 * i];
        float4 v1 = ((const float4*)in)[2 * i + 1];
        float4 a, b;
        a.x = __uint_as_float(f2tf32(v0.x)); a.y = __uint_as_float(f2tf32(v1.x));
        a.z = __uint_as_float(f2tf32(v0.y)); a.w = __uint_as_float(f2tf32(v1.y));
        b.x = __uint_as_float(f2tf32(v0.z)); b.y = __uint_as_float(f2tf32(v1.z));
        b.z = __uint_as_float(f2tf32(v0.w)); b.w = __uint_as_float(f2tf32(v1.w));
        ((float4*)out)[2 * i]     = a;
        ((float4*)out)[2 * i + 1] = b;
    }
}

// ---------------------------------------------------------------------------
// Prepass: transpose + tf32-round + K-octet-permute: in[K][N] -> out[N][Kperm]
// ---------------------------------------------------------------------------
__global__ void transpose_cvt_perm(const float* __restrict__ in,
                                   float* __restrict__ out, int R /*K*/,
                                   int Ccols /*N*/)
{
    __shared__ float t[32][33];
    const int cb = blockIdx.x * 32;    // N dim
    const int rb = blockIdx.y * 32;    // K dim
    const int tx = threadIdx.x, ty = threadIdx.y;   // 32 x 8
    #pragma unroll
    for (int i = 0; i < 32; i += 8)
        t[ty + i][tx] = in[(size_t)(rb + ty + i) * Ccols + cb + tx];
    __syncthreads();
    const int kp = rb + (tx & ~7) + 2 * (tx & 3) + ((tx >> 2) & 1);
    #pragma unroll
    for (int i = 0; i < 32; i += 8)
        out[(size_t)(cb + ty + i) * R + kp] =
            __uint_as_float(f2tf32(t[tx][ty + i]));
}

// ---------------------------------------------------------------------------
// tf32 tensor-core GEMM: C = A @ B' (+ epilogue).
// A: [M][Kperm] tf32.  B': [N][Kperm] tf32 (= B transposed).
// CTA = 128 threads (4 warps, 2x2), tile 128x128, warp tile 64x64, BK=32.
// Both operands cp.async-staged as [row][32] floats with 16B-chunk swizzle
// ch ^= 2*(row&3). Fragment loads are single conflict-free LDS.64 per
// operand (pair (k,k+4) adjacent thanks to the gmem octet permutation).
// 2-stage pipeline; 3 CTAs/SM. MODE 0 (QKV): q cols scaled, tf32 out.
// MODE 1 (proj): + bias, fp32 out. Dyn smem 64 KB.
// ---------------------------------------------------------------------------
#define GEMM_SMEM (16384 * 4)

template <int MODE>
__global__ __launch_bounds__(128, 3)
void tgemm_kernel(const float* __restrict__ A, const float* __restrict__ B,
                  const float* __restrict__ bias, float* __restrict__ C,
                  int M, int N, int K)
{
    extern __shared__ float smg[];
    const uint32_t sbase = (uint32_t)__cvta_generic_to_shared(smg);

    const int tid  = threadIdx.x;
    const int lane = tid & 31;
    const int warp = tid >> 5;
    const int m0 = blockIdx.y * 128;
    const int n0 = blockIdx.x * 128;
    const int wr = (warp & 1) * 64;   // warp m offset
    const int wn = (warp >> 1) * 64;  // warp n offset
    const int r0 = lane >> 2;         // 0..7
    const int c0 = lane & 3;          // 0..3

    float c[4][8][4];
    #pragma unroll
    for (int mi = 0; mi < 4; mi++)
        #pragma unroll
        for (int ni = 0; ni < 8; ni++)
            #pragma unroll
            for (int j = 0; j < 4; j++) c[mi][ni][j] = 0.0f;

    const float* Abase = A + (size_t)m0 * K;
    const float* Bbase = B + (size_t)n0 * K;
    const int nk = K / 32;

    // Stage one k-block: A and B each 128 rows x 8 chunks of 16B
    auto cpStage = [&](int kb, int s) {
        #pragma unroll
        for (int i = 0; i < 8; i++) {
            int id  = i * 128 + tid;
            int row = id >> 3;
            int ch  = id & 7;
            uint32_t off = (uint32_t)(s * 4096 + row * 32 +
                                      ((ch ^ (2 * (row & 3))) << 2)) * 4;
            cp_async16(sbase + off, Abase + (size_t)row * K + kb * 32 + ch * 4);
        }
        #pragma unroll
        for (int i = 0; i < 8; i++) {
            int id  = i * 128 + tid;
            int row = id >> 3;
            int ch  = id & 7;
            uint32_t off = (uint32_t)(8192 + s * 4096 + row * 32 +
                                      ((ch ^ (2 * (row & 3))) << 2)) * 4;
            cp_async16(sbase + off, Bbase + (size_t)row * K + kb * 32 + ch * 4);
        }
        cp_async_commit();
    };

    // Prologue: stage blocks 0 and 1
    cpStage(0, 0);
    cpStage(1, 1);

    for (int kb = 0; kb < nk; kb++) {
        const int buf = kb & 1;
        if (kb + 1 < nk) cp_async_wait1(); else cp_async_wait0();
        __syncthreads();

        const float* As = smg + buf * 4096;
        const float* Bs = smg + 8192 + buf * 4096;
        #pragma unroll
        for (int g = 0; g < 4; g++) {
            // shared swizzled word offset for this k-subgroup (hoisted by ptxas)
            const int o = (((2 * g + (c0 >> 1)) ^ (2 * (r0 & 3))) << 2) + 2 * (c0 & 1);
            uint32_t b[8][2];
            #pragma unroll
            for (int ni = 0; ni < 8; ni++) {
                uint2 bv = *(const uint2*)&Bs[(wn + ni * 8 + r0) * 32 + o];
                b[ni][0] = bv.x; b[ni][1] = bv.y;
            }
            #pragma unroll
            for (int mi = 0; mi < 4; mi++) {
                uint2 lo = *(const uint2*)&As[(wr + mi * 16 + r0)     * 32 + o];
                uint2 hi = *(const uint2*)&As[(wr + mi * 16 + 8 + r0) * 32 + o];
                uint32_t a[4] = {lo.x, hi.x, lo.y, hi.y};
                #pragma unroll
                for (int ni = 0; ni < 8; ni++) mma_tf32(c[mi][ni], a, b[ni]);
            }
        }

        __syncthreads();
        if (kb + 2 < nk) cpStage(kb + 2, buf);
    }

    // Epilogue (natural column order)
    #pragma unroll
    for (int mi = 0; mi < 4; mi++) {
        #pragma unroll
        for (int ni = 0; ni < 8; ni++) {
            int row = m0 + wr + mi * 16 + r0;
            int col = n0 + wn + ni * 8 + 2 * c0;
            float2 v0, v1;
            v0.x = c[mi][ni][0]; v0.y = c[mi][ni][1];
            v1.x = c[mi][ni][2]; v1.y = c[mi][ni][3];
            if (MODE == 0) {
                const float sc = (col < Cc) ? SC_Q : 1.0f;
                v0.x = __uint_as_float(f2tf32(v0.x * sc));
                v0.y = __uint_as_float(f2tf32(v0.y * sc));
                v1.x = __uint_as_float(f2tf32(v1.x * sc));
                v1.y = __uint_as_float(f2tf32(v1.y * sc));
            } else {
                float bx = bias[col], by = bias[col + 1];
                v0.x += bx; v0.y += by;
                v1.x += bx; v1.y += by;
            }
            *(float2*)(C + (size_t)row * N + col)       = v0;
            *(float2*)(C + (size_t)(row + 8) * N + col) = v1;
        }
    }
}

// ---------------------------------------------------------------------------
// Tensor-core flash attention (tf32 mma, causal) — R12 config (8 warps x 32
// q-rows, 256 thr). cp.async double-buffered 64-key K/V tiles; per-warp
// causal skip. qkv tf32 with q pre-scaled. OUTPUT IS K-OCTET-PERMUTED
// (feeds the proj GEMM's permuted-A layout).
// Smem: 2 x (K[64*68] + V[64*68]) + 8 warps x P[32*36] = 104 KB.
// ---------------------------------------------------------------------------
#define KVF   (64 * 68)                 // floats per K (or V) tile
#define ATT_SMEM ((4 * KVF + 8 * 32 * 36) * 4)

__global__ __launch_bounds__(256, 1)
void flash_tc_kernel(const float* __restrict__ qkv, float* __restrict__ out)
{
    extern __shared__ float sm[];
    const uint32_t sbase = (uint32_t)__cvta_generic_to_shared(sm);

    const int tid  = threadIdx.x;
    const int lane = tid & 31;
    const int warp = tid >> 5;
    const int r0 = lane >> 2;         // 0..7
    const int c0 = lane & 3;          // 0..3

    float* Phi = sm + 4 * KVF + warp * (32 * 36);

    const int bh = blockIdx.x;        // 0..63
    const int b  = bh >> 4;
    const int h  = bh & 15;
    const int q0 = (7 - (int)blockIdx.y) * 256;   // heavy blocks first
    const int wr = warp * 32;

    // Q fragments -> registers (already tf32 + scaled)
    uint32_t qa[2][8][4];
    {
        const float* qb = qkv + ((size_t)(b * Tt + q0 + wr)) * NQKV + h * HSd;
        #pragma unroll
        for (int mi = 0; mi < 2; mi++)
            #pragma unroll
            for (int ks = 0; ks < 8; ks++) {
                const float* p0 = qb + (size_t)(mi * 16 + r0)     * NQKV + ks * 8 + c0;
                const float* p1 = qb + (size_t)(mi * 16 + 8 + r0) * NQKV + ks * 8 + c0;
                qa[mi][ks][0] = __float_as_uint(p0[0]);
                qa[mi][ks][1] = __float_as_uint(p1[0]);
                qa[mi][ks][2] = __float_as_uint(p0[4]);
                qa[mi][ks][3] = __float_as_uint(p1[4]);
            }
    }

    float o[2][8][4];
    #pragma unroll
    for (int mi = 0; mi < 2; mi++)
        #pragma unroll
        for (int ni = 0; ni < 8; ni++)
            #pragma unroll
            for (int j = 0; j < 4; j++) o[mi][ni][j] = 0.0f;
    float mrow[4], lrow[4];
    #pragma unroll
    for (int rs = 0; rs < 4; rs++) { mrow[rs] = -1e30f; lrow[rs] = 0.0f; }

    const float* kgb = qkv + ((size_t)b * Tt) * NQKV + Cc + h * HSd;
    const float* vgb = kgb + Cc;

    const int ntiles = q0 / 64 + 4;
    const int firstMaskTile = (q0 + wr) >> 6;    // per-warp
    const int lastRow = q0 + wr + 31;            // last q-row this warp owns

    auto cpKV = [&](int kt, int s) {
        const float* kg = kgb + (size_t)(kt * 64) * NQKV;
        const float* vg = vgb + (size_t)(kt * 64) * NQKV;
        #pragma unroll
        for (int i = 0; i < 4; i++) {
            int idx = i * 256 + tid;          // 0..1023
            int row = idx >> 4;
            int cc4 = (idx & 15) << 2;
            uint32_t doff = (uint32_t)(s * 2 * KVF + row * 68 + cc4) * 4;
            cp_async16(sbase + doff,           kg + (size_t)row * NQKV + cc4);
            cp_async16(sbase + doff + KVF * 4, vg + (size_t)row * NQKV + cc4);
        }
        cp_async_commit();
    };

    cpKV(0, 0);

    for (int kt = 0; kt < ntiles; kt++) {
        const int buf = kt & 1;
        if (kt + 1 < ntiles) { cpKV(kt + 1, buf ^ 1); cp_async_wait1(); }
        else cp_async_wait0();
        __syncthreads();

        if (kt * 64 <= lastRow) {
            const float* Ksm = sm + buf * 2 * KVF;
            const float* Vsm = Ksm + KVF;

            // S = Q K^T
            float s[2][8][4];
            #pragma unroll
            for (int mi = 0; mi < 2; mi++)
                #pragma unroll
                for (int ni = 0; ni < 8; ni++)
                    #pragma unroll
                    for (int j = 0; j < 4; j++) s[mi][ni][j] = 0.0f;

            #pragma unroll
            for (int ks = 0; ks < 8; ks++) {
                #pragma unroll
                for (int ni = 0; ni < 8; ni++) {
                    uint32_t bb[2];
                    bb[0] = __float_as_uint(Ksm[(ni * 8 + r0) * 68 + ks * 8 + c0]);
                    bb[1] = __float_as_uint(Ksm[(ni * 8 + r0) * 68 + ks * 8 + c0 + 4]);
                    mma_tf32(s[0][ni], qa[0][ks], bb);
                    mma_tf32(s[1][ni], qa[1][ks], bb);
                }
            }

            // Causal mask (per-warp diagonal tiles only)
            if (kt >= firstMaskTile) {
                #pragma unroll
                for (int mi = 0; mi < 2; mi++) {
                    int row = q0 + wr + mi * 16 + r0;
                    #pragma unroll
                    for (int ni = 0; ni < 8; ni++) {
                        int key = kt * 64 + ni * 8 + 2 * c0;
                        if (key     > row)     s[mi][ni][0] = -1e30f;
                        if (key + 1 > row)     s[mi][ni][1] = -1e30f;
                        if (key     > row + 8) s[mi][ni][2] = -1e30f;
                        if (key + 1 > row + 8) s[mi][ni][3] = -1e30f;
                    }
                }
            }

            // Online softmax (exp2 domain); s becomes p
            #pragma unroll
            for (int mi = 0; mi < 2; mi++) {
                #pragma unroll
                for (int h2 = 0; h2 < 2; h2++) {
                    const int rs = mi * 2 + h2;
                    float mx = -1e30f;
                    #pragma unroll
                    for (int ni = 0; ni < 8; ni++)
                        mx = fmaxf(mx, fmaxf(s[mi][ni][2 * h2], s[mi][ni][2 * h2 + 1]));
                    mx = fmaxf(mx, __shfl_xor_sync(0xffffffffu, mx, 1));
                    mx = fmaxf(mx, __shfl_xor_sync(0xffffffffu, mx, 2));
                    float mnew = fmaxf(mrow[rs], mx);
                    float corr = exp2fast(mrow[rs] - mnew);
                    mrow[rs] = mnew;
                    float psum = 0.0f;
                    #pragma unroll
                    for (int ni = 0; ni < 8; ni++) {
                        float p0 = exp2fast(s[mi][ni][2 * h2]     - mnew);
                        float p1 = exp2fast(s[mi][ni][2 * h2 + 1] - mnew);
                        s[mi][ni][2 * h2]     = p0;
                        s[mi][ni][2 * h2 + 1] = p1;
                        psum += p0 + p1;
                    }
                    lrow[rs] = lrow[rs] * corr + psum;
                    #pragma unroll
                    for (int ni = 0; ni < 8; ni++) {
                        o[mi][ni][2 * h2]     *= corr;
                        o[mi][ni][2 * h2 + 1] *= corr;
                    }
                }
            }

            // O += P V, two 32-key halves (P tf32 via per-warp smem)
            #pragma unroll
            for (int hk = 0; hk < 2; hk++) {
                #pragma unroll
                for (int mi = 0; mi < 2; mi++) {
                    #pragma unroll
                    for (int h2 = 0; h2 < 2; h2++) {
                        int rloc = mi * 16 + h2 * 8 + r0;
                        #pragma unroll
                        for (int j = 0; j < 4; j++) {
                            float h0 = __uint_as_float(f2tf32(s[mi][hk * 4 + j][2 * h2]));
                            float h1 = __uint_as_float(f2tf32(s[mi][hk * 4 + j][2 * h2 + 1]));
                            *(float2*)&Phi[rloc * 36 + j * 8 + 2 * c0] = make_float2(h0, h1);
                        }
                    }
                }
                __syncwarp();
                #pragma unroll
                for (int ks = 0; ks < 4; ks++) {
                    uint32_t ah[2][4];
                    #pragma unroll
                    for (int mi = 0; mi < 2; mi++) {
                        int ra = mi * 16 + r0;
                        ah[mi][0] = __float_as_uint(Phi[ra * 36 + ks * 8 + c0]);
                        ah[mi][1] = __float_as_uint(Phi[(ra + 8) * 36 + ks * 8 + c0]);
                        ah[mi][2] = __float_as_uint(Phi[ra * 36 + ks * 8 + c0 + 4]);
                        ah[mi][3] = __float_as_uint(Phi[(ra + 8) * 36 + ks * 8 + c0 + 4]);
                    }
                    #pragma unroll
                    for (int ni = 0; ni < 8; ni++) {
                        uint32_t bb[2];
                        int vrow = hk * 32 + ks * 8 + c0;
                        bb[0] = __float_as_uint(Vsm[vrow * 68 + ni * 8 + r0]);
                        bb[1] = __float_as_uint(Vsm[(vrow + 4) * 68 + ni * 8 + r0]);
                        mma_tf32(o[0][ni], ah[0], bb);
                        mma_tf32(o[1][ni], ah[1], bb);
                    }
                }
                __syncwarp();
            }
        }

        __syncthreads();   // all warps done with buf before next prefetch overwrites it
    }

    // Final normalize + tf32-round + K-OCTET-PERMUTED write (proj GEMM layout)
    float linv[4];
    #pragma unroll
    for (int rs = 0; rs < 4; rs++) {
        float l = lrow[rs];
        l += __shfl_xor_sync(0xffffffffu, l, 1);
        l += __shfl_xor_sync(0xffffffffu, l, 2);
        linv[rs] = 1.0f / l;
    }
    // perm(w) = 2*(w&3) + ((w>>2)&1) for w = 2c0 and 2c0+1
    const int p0 = 2 * ((2 * c0) & 3) + (((2 * c0) >> 2) & 1);
    const int p1 = 2 * ((2 * c0 + 1) & 3) + (((2 * c0 + 1) >> 2) & 1);
    float* ob = out + ((size_t)(b * Tt + q0 + wr)) * Cc + h * HSd;
    #pragma unroll
    for (int mi = 0; mi < 2; mi++) {
        #pragma unroll
        for (int h2 = 0; h2 < 2; h2++) {
            int rloc = mi * 16 + h2 * 8 + r0;
            float inv = linv[mi * 2 + h2];
            #pragma unroll
            for (int ni = 0; ni < 8; ni++) {
                float vx = __uint_as_float(f2tf32(o[mi][ni][2 * h2]     * inv));
                float vy = __uint_as_float(f2tf32(o[mi][ni][2 * h2 + 1] * inv));
                ob[(size_t)rloc * Cc + ni * 8 + p0] = vx;
                ob[(size_t)rloc * Cc + ni * 8 + p1] = vy;
            }
        }
    }
}

// ---------------------------------------------------------------------------
extern "C" void kernel_launch(void* const* d_in, const int* in_sizes, int n_in,
                              void* d_out, int out_size)
{
    const float* x     = (const float*)d_in[0];   // [B,T,C]
    const float* Wqkv  = (const float*)d_in[1];   // [C,3C]
    const float* Wproj = (const float*)d_in[2];   // [C,C]
    const float* bproj = (const float*)d_in[3];   // [C]
    float* out = (float*)d_out;                   // [B,T,C]

    float *qkv, *attn, *xc, *wqkvc, *wprojc;
    cudaGetSymbolAddress((void**)&qkv,    g_qkv);
    cudaGetSymbolAddress((void**)&attn,   g_attn);
    cudaGetSymbolAddress((void**)&xc,     g_xc);
    cudaGetSymbolAddress((void**)&wqkvc,  g_wqkv_c);
    cudaGetSymbolAddress((void**)&wprojc, g_wproj_c);

    cudaFuncSetAttribute(tgemm_kernel<0>,
                         cudaFuncAttributeMaxDynamicSharedMemorySize, GEMM_SMEM);
    cudaFuncSetAttribute(tgemm_kernel<1>,
                         cudaFuncAttributeMaxDynamicSharedMemorySize, GEMM_SMEM);
    cudaFuncSetAttribute(flash_tc_kernel,
                         cudaFuncAttributeMaxDynamicSharedMemorySize, ATT_SMEM);

    // Prepass: x -> tf32 + K-permuted; weights -> transposed [N][K] tf32 + K-permuted
    cvt_perm_kernel<<<(Mm * Cc / 8 + 255) / 256, 256>>>(x, xc, Mm * Cc / 8);
    transpose_cvt_perm<<<dim3(NQKV / 32, Cc / 32), dim3(32, 8)>>>(Wqkv, wqkvc, Cc, NQKV);
    transpose_cvt_perm<<<dim3(Cc / 32, Cc / 32), dim3(32, 8)>>>(Wproj, wprojc, Cc, Cc);

    // 1) QKV projection: [8192,1024] @ [1024,3072] -> tf32 qkv (q pre-scaled)
    tgemm_kernel<0><<<dim3(NQKV / 128, Mm / 128), 128, GEMM_SMEM>>>(
        xc, wqkvc, nullptr, qkv, Mm, NQKV, Cc);
    // 2) Causal flash attention -> tf32 K-permuted [B,T,C]
    flash_tc_kernel<<<dim3(Bb * Hh, Tt / 256), 256, ATT_SMEM>>>(qkv, attn);
    // 3) Output projection + bias: [8192,1024] @ [1024,1024]
    tgemm_kernel<1><<<dim3(Cc / 128, Mm / 128), 128, GEMM_SMEM>>>(
        attn, wprojc, bproj, out, Mm, Cc, Cc);
}

// round 17
// speedup vs baseline: 1.1140x; 1.0409x over previous
#include <cuda_runtime.h>
#include <math.h>
#include <stdint.h>

// Problem constants
#define Bb   4
#define Tt   2048
#define Cc   1024
#define Hh   16
#define HSd  64
#define Mm   (Bb * Tt)      // 8192
#define NQKV (3 * Cc)       // 3072

// Scratch (static device globals: allocation rules forbid cudaMalloc)
__device__ float g_qkv[(size_t)Mm * NQKV];     // [B*T, 3C] tf32 (q pre-scaled by SC_Q)
__device__ float g_attn[(size_t)Mm * Cc];      // [B*T, C] tf32 attention out
__device__ float g_xc[(size_t)Mm * Cc];        // x, tf32
__device__ float g_wqkv_c[(size_t)Cc * NQKV];  // W_qkv, tf32, [K][N]
__device__ float g_wproj_c[(size_t)Cc * Cc];   // W_proj, tf32, [K][N]

// ---------------------------------------------------------------------------
// helpers
// ---------------------------------------------------------------------------
static __device__ __forceinline__ uint32_t f2tf32(float x) {
    uint32_t y;
    asm("cvt.rna.tf32.f32 %0, %1;" : "=r"(y) : "f"(x));
    return y;
}

static __device__ __forceinline__ float exp2fast(float x) {
    float y;
    asm("ex2.approx.f32 %0, %1;" : "=f"(y) : "f"(x));
    return y;
}

static __device__ __forceinline__ void mma_tf32(float c[4], const uint32_t a[4],
                                                const uint32_t b[2]) {
    asm volatile(
        "mma.sync.aligned.m16n8k8.row.col.f32.tf32.tf32.f32 "
        "{%0,%1,%2,%3}, {%4,%5,%6,%7}, {%8,%9}, {%0,%1,%2,%3};\n"
        : "+f"(c[0]), "+f"(c[1]), "+f"(c[2]), "+f"(c[3])
        : "r"(a[0]), "r"(a[1]), "r"(a[2]), "r"(a[3]), "r"(b[0]), "r"(b[1]));
}

static __device__ __forceinline__ void cp_async16(uint32_t smem_dst,
                                                  const void* gsrc) {
    asm volatile("cp.async.cg.shared.global [%0], [%1], 16;"
                 :: "r"(smem_dst), "l"(gsrc) : "memory");
}
static __device__ __forceinline__ void cp_async_commit() {
    asm volatile("cp.async.commit_group;" ::: "memory");
}
static __device__ __forceinline__ void cp_async_wait0() {
    asm volatile("cp.async.wait_group 0;" ::: "memory");
}
static __device__ __forceinline__ void cp_async_wait1() {
    asm volatile("cp.async.wait_group 1;" ::: "memory");
}

#define SC_Q (0.125f * 1.4426950408889634f)   // (1/sqrt(64)) * log2(e)

// ---------------------------------------------------------------------------
// Prepass (single launch): tf32-round x, W_qkv, W_proj (layouts unchanged)
// Region-partitioned linear grid over float4 groups.
// ---------------------------------------------------------------------------
#define N4_X  (Mm * Cc / 4)        // 2,097,152
#define N4_W1 (Cc * NQKV / 4)      //   786,432
#define N4_W2 (Cc * Cc / 4)        //   262,144

__global__ void cvt3_kernel(const float* __restrict__ x,  float* __restrict__ xc,
                            const float* __restrict__ w1, float* __restrict__ w1c,
                            const float* __restrict__ w2, float* __restrict__ w2c)
{
    int i = blockIdx.x * blockDim.x + threadIdx.x;
    const float4* src;
    float4* dst;
    if (i < N4_X)                { src = (const float4*)x  + i;                 dst = (float4*)xc  + i; }
    else if (i < N4_X + N4_W1)   { src = (const float4*)w1 + (i - N4_X);        dst = (float4*)w1c + (i - N4_X); }
    else if (i < N4_X + N4_W1 + N4_W2) { src = (const float4*)w2 + (i - N4_X - N4_W1); dst = (float4*)w2c + (i - N4_X - N4_W1); }
    else return;
    float4 v = *src;
    v.x = __uint_as_float(f2tf32(v.x));
    v.y = __uint_as_float(f2tf32(v.y));
    v.z = __uint_as_float(f2tf32(v.z));
    v.w = __uint_as_float(f2tf32(v.w));
    *dst = v;
}

// ---------------------------------------------------------------------------
// tf32 tensor-core GEMM (R12 config): C = A @ B (+ epilogue). Inputs tf32.
// CTA = 128 threads (4 warps, 2x2), CTA tile 128x128, warp tile 64x64, BK=32.
// Both operands cp.async-staged; 2-stage pipeline; 3 CTAs/SM.
// A smem: [row][32], 16B-chunk swizzle c' = c ^ (row&7). B: [k][128],
// chunk swizzle ch' = ch ^ (2*(k&3)). Conflict-free fragment reads.
// MODE 0 (QKV): cols < Cc (q) scaled by SC_Q; outputs tf32-rounded.
// MODE 1 (proj): + bias, fp32 out. Dyn smem 64 KB.
// ---------------------------------------------------------------------------
#define GEMM_SMEM (16384 * 4)

template <int MODE>
__global__ __launch_bounds__(128, 3)
void tgemm_kernel(const float* __restrict__ A, const float* __restrict__ B,
                  const float* __restrict__ bias, float* __restrict__ C,
                  int M, int N, int K)
{
    extern __shared__ float smg[];
    const uint32_t sbase = (uint32_t)__cvta_generic_to_shared(smg);

    const int tid  = threadIdx.x;
    const int lane = tid & 31;
    const int warp = tid >> 5;
    const int m0 = blockIdx.y * 128;
    const int n0 = blockIdx.x * 128;
    const int wr = (warp & 1) * 64;   // warp m offset
    const int wn = (warp >> 1) * 64;  // warp n offset
    const int r0 = lane >> 2;         // 0..7
    const int c0 = lane & 3;          // 0..3
    const int xr = 8 * c0;            // read-side B swizzle

    float c[4][8][4];
    #pragma unroll
    for (int mi = 0; mi < 4; mi++)
        #pragma unroll
        for (int ni = 0; ni < 8; ni++)
            #pragma unroll
            for (int j = 0; j < 4; j++) c[mi][ni][j] = 0.0f;

    const float* Abase = A + (size_t)m0 * K;
    const float* Bbase = B + n0;
    const int nk = K / 32;

    auto cpStage = [&](int kb, int s) {
        #pragma unroll
        for (int i = 0; i < 8; i++) {
            int id  = i * 128 + tid;
            int row = id >> 3;
            int ch  = id & 7;
            uint32_t dst = sbase +
                (uint32_t)(s * 4096 + row * 32 + ((ch ^ (row & 7)) << 2)) * 4;
            cp_async16(dst, Abase + (size_t)row * K + kb * 32 + ch * 4);
        }
        #pragma unroll
        for (int i = 0; i < 8; i++) {
            int id  = i * 128 + tid;
            int row = id >> 5;
            int ch  = id & 31;
            uint32_t dst = sbase +
                (uint32_t)(8192 + s * 4096 + row * 128 + ((ch ^ (2 * (row & 3))) << 2)) * 4;
            cp_async16(dst, Bbase + (size_t)(kb * 32 + row) * N + ch * 4);
        }
        cp_async_commit();
    };

    // Prologue: stage blocks 0 and 1
    cpStage(0, 0);
    cpStage(1, 1);

    for (int kb = 0; kb < nk; kb++) {
        const int buf = kb & 1;
        if (kb + 1 < nk) cp_async_wait1(); else cp_async_wait0();
        __syncthreads();

        const float* As = smg + buf * 4096;
        const float* Bs = smg + 8192 + buf * 4096;
        #pragma unroll
        for (int g = 0; g < 4; g++) {
            uint32_t b[8][2];
            #pragma unroll
            for (int ni = 0; ni < 8; ni++) {
                int coln = (wn + ni * 8 + r0) ^ xr;
                b[ni][0] = __float_as_uint(Bs[(g * 8 + c0)     * 128 + coln]);
                b[ni][1] = __float_as_uint(Bs[(g * 8 + c0 + 4) * 128 + coln]);
            }
            const int sw0 = (((2 * g)     ^ r0) << 2) + c0;
            const int sw1 = (((2 * g + 1) ^ r0) << 2) + c0;
            #pragma unroll
            for (int mi = 0; mi < 4; mi++) {
                const int ra = (wr + mi * 16 + r0) * 32;
                uint32_t a[4];
                a[0] = __float_as_uint(As[ra       + sw0]);
                a[1] = __float_as_uint(As[ra + 256 + sw0]);   // +8 rows
                a[2] = __float_as_uint(As[ra       + sw1]);
                a[3] = __float_as_uint(As[ra + 256 + sw1]);
                #pragma unroll
                for (int ni = 0; ni < 8; ni++) mma_tf32(c[mi][ni], a, b[ni]);
            }
        }

        __syncthreads();
        if (kb + 2 < nk) cpStage(kb + 2, buf);
    }

    // Epilogue
    #pragma unroll
    for (int mi = 0; mi < 4; mi++) {
        #pragma unroll
        for (int ni = 0; ni < 8; ni++) {
            int row = m0 + wr + mi * 16 + r0;
            int col = n0 + wn + ni * 8 + 2 * c0;
            float2 v0, v1;
            v0.x = c[mi][ni][0]; v0.y = c[mi][ni][1];
            v1.x = c[mi][ni][2]; v1.y = c[mi][ni][3];
            if (MODE == 0) {
                const float sc = (col < Cc) ? SC_Q : 1.0f;
                v0.x = __uint_as_float(f2tf32(v0.x * sc));
                v0.y = __uint_as_float(f2tf32(v0.y * sc));
                v1.x = __uint_as_float(f2tf32(v1.x * sc));
                v1.y = __uint_as_float(f2tf32(v1.y * sc));
            } else {
                float bx = bias[col], by = bias[col + 1];
                v0.x += bx; v0.y += by;
                v1.x += bx; v1.y += by;
            }
            *(float2*)(C + (size_t)row * N + col)       = v0;
            *(float2*)(C + (size_t)(row + 8) * N + col) = v1;
        }
    }
}

// ---------------------------------------------------------------------------
// Tensor-core flash attention (tf32 mma, causal). 8 warps x 32 q-rows.
// 128-KEY double-buffered cp.async stages, computed as two 64-key halves:
// halves the barrier/wait count per key. Per-warp causal skip.
// qkv tf32 with q pre-scaled; output tf32-rounded.
// Smem: 2 stages x (K[128*68] + V[128*68]) + 8 x P[32*36] = 176 KB.
// ---------------------------------------------------------------------------
#define KVF128 (128 * 68)               // floats per 128-key K (or V) stage
#define ATT_SMEM ((4 * KVF128 + 8 * 32 * 36) * 4)

__global__ __launch_bounds__(256, 1)
void flash_tc_kernel(const float* __restrict__ qkv, float* __restrict__ out)
{
    extern __shared__ float sm[];
    const uint32_t sbase = (uint32_t)__cvta_generic_to_shared(sm);

    const int tid  = threadIdx.x;
    const int lane = tid & 31;
    const int warp = tid >> 5;
    const int r0 = lane >> 2;         // 0..7
    const int c0 = lane & 3;          // 0..3

    float* Phi = sm + 4 * KVF128 + warp * (32 * 36);

    const int bh = blockIdx.x;        // 0..63
    const int b  = bh >> 4;
    const int h  = bh & 15;
    const int q0 = (7 - (int)blockIdx.y) * 256;   // heavy blocks first
    const int wr = warp * 32;

    // Q fragments -> registers (already tf32 + scaled)
    uint32_t qa[2][8][4];
    {
        const float* qb = qkv + ((size_t)(b * Tt + q0 + wr)) * NQKV + h * HSd;
        #pragma unroll
        for (int mi = 0; mi < 2; mi++)
            #pragma unroll
            for (int ks = 0; ks < 8; ks++) {
                const float* p0 = qb + (size_t)(mi * 16 + r0)     * NQKV + ks * 8 + c0;
                const float* p1 = qb + (size_t)(mi * 16 + 8 + r0) * NQKV + ks * 8 + c0;
                qa[mi][ks][0] = __float_as_uint(p0[0]);
                qa[mi][ks][1] = __float_as_uint(p1[0]);
                qa[mi][ks][2] = __float_as_uint(p0[4]);
                qa[mi][ks][3] = __float_as_uint(p1[4]);
            }
    }

    float o[2][8][4];
    #pragma unroll
    for (int mi = 0; mi < 2; mi++)
        #pragma unroll
        for (int ni = 0; ni < 8; ni++)
            #pragma unroll
            for (int j = 0; j < 4; j++) o[mi][ni][j] = 0.0f;
    float mrow[4], lrow[4];
    #pragma unroll
    for (int rs = 0; rs < 4; rs++) { mrow[rs] = -1e30f; lrow[rs] = 0.0f; }

    const float* kgb = qkv + ((size_t)b * Tt) * NQKV + Cc + h * HSd;
    const float* vgb = kgb + Cc;

    const int ntiles = q0 / 64 + 4;          // always a multiple of 4 -> even
    const int nst    = ntiles / 2;           // 128-key stages
    const int firstMaskTile = (q0 + wr) >> 6;    // per-warp (64-key units)
    const int lastRow = q0 + wr + 31;            // last q-row this warp owns

    // Stage 128 keys of K and V (128 rows x 16 chunks each array)
    auto cpKV = [&](int st, int s) {
        const float* kg = kgb + (size_t)(st * 128) * NQKV;
        const float* vg = vgb + (size_t)(st * 128) * NQKV;
        #pragma unroll
        for (int i = 0; i < 8; i++) {
            int idx = i * 256 + tid;          // 0..2047
            int row = idx >> 4;
            int cc4 = (idx & 15) << 2;
            uint32_t doff = (uint32_t)(s * 2 * KVF128 + row * 68 + cc4) * 4;
            cp_async16(sbase + doff,              kg + (size_t)row * NQKV + cc4);
            cp_async16(sbase + doff + KVF128 * 4, vg + (size_t)row * NQKV + cc4);
        }
        cp_async_commit();
    };

    cpKV(0, 0);

    for (int st = 0; st < nst; st++) {
        const int buf = st & 1;
        if (st + 1 < nst) { cpKV(st + 1, buf ^ 1); cp_async_wait1(); }
        else cp_async_wait0();
        __syncthreads();

        #pragma unroll 1
        for (int hh = 0; hh < 2; hh++) {
            const int kt = st * 2 + hh;          // 64-key tile index
            if (kt * 64 > lastRow) break;        // per-warp causal skip

            const float* Ksm = sm + buf * 2 * KVF128 + hh * (64 * 68);
            const float* Vsm = sm + buf * 2 * KVF128 + KVF128 + hh * (64 * 68);

            // S = Q K^T
            float s[2][8][4];
            #pragma unroll
            for (int mi = 0; mi < 2; mi++)
                #pragma unroll
                for (int ni = 0; ni < 8; ni++)
                    #pragma unroll
                    for (int j = 0; j < 4; j++) s[mi][ni][j] = 0.0f;

            #pragma unroll
            for (int ks = 0; ks < 8; ks++) {
                #pragma unroll
                for (int ni = 0; ni < 8; ni++) {
                    uint32_t bb[2];
                    bb[0] = __float_as_uint(Ksm[(ni * 8 + r0) * 68 + ks * 8 + c0]);
                    bb[1] = __float_as_uint(Ksm[(ni * 8 + r0) * 68 + ks * 8 + c0 + 4]);
                    mma_tf32(s[0][ni], qa[0][ks], bb);
                    mma_tf32(s[1][ni], qa[1][ks], bb);
                }
            }

            // Causal mask (per-warp diagonal tiles only)
            if (kt >= firstMaskTile) {
                #pragma unroll
                for (int mi = 0; mi < 2; mi++) {
                    int row = q0 + wr + mi * 16 + r0;
                    #pragma unroll
                    for (int ni = 0; ni < 8; ni++) {
                        int key = kt * 64 + ni * 8 + 2 * c0;
                        if (key     > row)     s[mi][ni][0] = -1e30f;
                        if (key + 1 > row)     s[mi][ni][1] = -1e30f;
                        if (key     > row + 8) s[mi][ni][2] = -1e30f;
                        if (key + 1 > row + 8) s[mi][ni][3] = -1e30f;
                    }
                }
            }

            // Online softmax (exp2 domain); s becomes p
            #pragma unroll
            for (int mi = 0; mi < 2; mi++) {
                #pragma unroll
                for (int h2 = 0; h2 < 2; h2++) {
                    const int rs = mi * 2 + h2;
                    float mx = -1e30f;
                    #pragma unroll
                    for (int ni = 0; ni < 8; ni++)
                        mx = fmaxf(mx, fmaxf(s[mi][ni][2 * h2], s[mi][ni][2 * h2 + 1]));
                    mx = fmaxf(mx, __shfl_xor_sync(0xffffffffu, mx, 1));
                    mx = fmaxf(mx, __shfl_xor_sync(0xffffffffu, mx, 2));
                    float mnew = fmaxf(mrow[rs], mx);
                    float corr = exp2fast(mrow[rs] - mnew);
                    mrow[rs] = mnew;
                    float psum = 0.0f;
                    #pragma unroll
                    for (int ni = 0; ni < 8; ni++) {
                        float p0 = exp2fast(s[mi][ni][2 * h2]     - mnew);
                        float p1 = exp2fast(s[mi][ni][2 * h2 + 1] - mnew);
                        s[mi][ni][2 * h2]     = p0;
                        s[mi][ni][2 * h2 + 1] = p1;
                        psum += p0 + p1;
                    }
                    lrow[rs] = lrow[rs] * corr + psum;
                    #pragma unroll
                    for (int ni = 0; ni < 8; ni++) {
                        o[mi][ni][2 * h2]     *= corr;
                        o[mi][ni][2 * h2 + 1] *= corr;
                    }
                }
            }

            // O += P V, two 32-key halves (P tf32 via per-warp smem)
            #pragma unroll
            for (int hk = 0; hk < 2; hk++) {
                #pragma unroll
                for (int mi = 0; mi < 2; mi++) {
                    #pragma unroll
                    for (int h2 = 0; h2 < 2; h2++) {
                        int rloc = mi * 16 + h2 * 8 + r0;
                        #pragma unroll
                        for (int j = 0; j < 4; j++) {
                            float h0 = __uint_as_float(f2tf32(s[mi][hk * 4 + j][2 * h2]));
                            float h1 = __uint_as_float(f2tf32(s[mi][hk * 4 + j][2 * h2 + 1]));
                            *(float2*)&Phi[rloc * 36 + j * 8 + 2 * c0] = make_float2(h0, h1);
                        }
                    }
                }
                __syncwarp();
                #pragma unroll
                for (int ks = 0; ks < 4; ks++) {
                    uint32_t ah[2][4];
                    #pragma unroll
                    for (int mi = 0; mi < 2; mi++) {
                        int ra = mi * 16 + r0;
                        ah[mi][0] = __float_as_uint(Phi[ra * 36 + ks * 8 + c0]);
                        ah[mi][1] = __float_as_uint(Phi[(ra + 8) * 36 + ks * 8 + c0]);
                        ah[mi][2] = __float_as_uint(Phi[ra * 36 + ks * 8 + c0 + 4]);
                        ah[mi][3] = __float_as_uint(Phi[(ra + 8) * 36 + ks * 8 + c0 + 4]);
                    }
                    #pragma unroll
                    for (int ni = 0; ni < 8; ni++) {
                        uint32_t bb[2];
                        int vrow = hk * 32 + ks * 8 + c0;
                        bb[0] = __float_as_uint(Vsm[vrow * 68 + ni * 8 + r0]);
                        bb[1] = __float_as_uint(Vsm[(vrow + 4) * 68 + ni * 8 + r0]);
                        mma_tf32(o[0][ni], ah[0], bb);
                        mma_tf32(o[1][ni], ah[1], bb);
                    }
                }
                __syncwarp();
            }
        }

        __syncthreads();   // all warps done with buf before next prefetch overwrites it
    }

    // Final normalize + tf32-round + write
    float linv[4];
    #pragma unroll
    for (int rs = 0; rs < 4; rs++) {
        float l = lrow[rs];
        l += __shfl_xor_sync(0xffffffffu, l, 1);
        l += __shfl_xor_sync(0xffffffffu, l, 2);
        linv[rs] = 1.0f / l;
    }
    float* ob = out + ((size_t)(b * Tt + q0 + wr)) * Cc + h * HSd;
    #pragma unroll
    for (int mi = 0; mi < 2; mi++) {
        #pragma unroll
        for (int h2 = 0; h2 < 2; h2++) {
            int rloc = mi * 16 + h2 * 8 + r0;
            float inv = linv[mi * 2 + h2];
            #pragma unroll
            for (int ni = 0; ni < 8; ni++) {
                float2 v;
                v.x = __uint_as_float(f2tf32(o[mi][ni][2 * h2]     * inv));
                v.y = __uint_as_float(f2tf32(o[mi][ni][2 * h2 + 1] * inv));
                *(float2*)(ob + (size_t)rloc * Cc + ni * 8 + 2 * c0) = v;
            }
        }
    }
}

// ---------------------------------------------------------------------------
extern "C" void kernel_launch(void* const* d_in, const int* in_sizes, int n_in,
                              void* d_out, int out_size)
{
    const float* x     = (const float*)d_in[0];   // [B,T,C]
    const float* Wqkv  = (const float*)d_in[1];   // [C,3C]
    const float* Wproj = (const float*)d_in[2];   // [C,C]
    const float* bproj = (const float*)d_in[3];   // [C]
    float* out = (float*)d_out;                   // [B,T,C]

    float *qkv, *attn, *xc, *wqkvc, *wprojc;
    cudaGetSymbolAddress((void**)&qkv,    g_qkv);
    cudaGetSymbolAddress((void**)&attn,   g_attn);
    cudaGetSymbolAddress((void**)&xc,     g_xc);
    cudaGetSymbolAddress((void**)&wqkvc,  g_wqkv_c);
    cudaGetSymbolAddress((void**)&wprojc, g_wproj_c);

    cudaFuncSetAttribute(tgemm_kernel<0>,
                         cudaFuncAttributeMaxDynamicSharedMemorySize, GEMM_SMEM);
    cudaFuncSetAttribute(tgemm_kernel<1>,
                         cudaFuncAttributeMaxDynamicSharedMemorySize, GEMM_SMEM);
    cudaFuncSetAttribute(flash_tc_kernel,
                         cudaFuncAttributeMaxDynamicSharedMemorySize, ATT_SMEM);

    // Prepass (single launch): tf32-round x + both weights
    {
        const int n4 = N4_X + N4_W1 + N4_W2;
        cvt3_kernel<<<(n4 + 255) / 256, 256>>>(x, xc, Wqkv, wqkvc, Wproj, wprojc);
    }

    // 1) QKV projection: [8192,1024] @ [1024,3072] -> tf32 qkv (q pre-scaled)
    tgemm_kernel<0><<<dim3(NQKV / 128, Mm / 128), 128, GEMM_SMEM>>>(
        xc, wqkvc, nullptr, qkv, Mm, NQKV, Cc);
    // 2) Causal flash attention -> tf32 [B,T,C]
    flash_tc_kernel<<<dim3(Bb * Hh, Tt / 256), 256, ATT_SMEM>>>(qkv, attn);
    // 3) Output projection + bias: [8192,1024] @ [1024,1024]
    tgemm_kernel<1><<<dim3(Cc / 128, Mm / 128), 128, GEMM_SMEM>>>(
        attn, wprojc, bproj, out, Mm, Cc, Cc);
}